// round 11
// baseline (speedup 1.0000x reference)
#include <cuda_runtime.h>

// InvConditionalLinear forward: per-pixel 32x32 solve W z = x, sum log|det W|.
// B=16, C=32, H=W=48 (HW=2304). 2 matrices per warp x 2 column-parity slices
// (four 8-lane subgroups). Lane owns 4 rows x 8 f32x2 blocks of its parity.
// R7-validated software-pipelined inner loop + genuine register trim
// (pisave removed; z recomputed by division at epilogue) to fit 5 blocks/SM.

#define FULL_MASK 0xffffffffu

static constexpr int B = 16, C = 32, HW = 48 * 48;     // 2304
static constexpr int PIX = 8;                          // pixels per block (128 thr)
static constexpr int RSTR = 36;                        // row stride (floats)
static constexpr int MSTR = 1156;                      // pixel stride: !=0 mod 8 banks
static constexpr int BLOCKS_PER_BATCH = HW / PIX;      // 288

static __device__ float g_pixlogdet[B * HW];
static __device__ int   g_done[B];

__device__ __forceinline__ unsigned long long pack2(float x, float y) {
    unsigned long long r;
    asm("mov.b64 %0, {%1, %2};" : "=l"(r) : "r"(__float_as_uint(x)), "r"(__float_as_uint(y)));
    return r;
}
__device__ __forceinline__ float lo32(unsigned long long v) { return __uint_as_float((unsigned)v); }
__device__ __forceinline__ float hi32(unsigned long long v) { return __uint_as_float((unsigned)(v >> 32)); }
__device__ __forceinline__ unsigned long long ffma2(unsigned long long a, unsigned long long b,
                                                    unsigned long long c) {
    unsigned long long d;
    asm("fma.rn.f32x2 %0, %1, %2, %3;" : "=l"(d) : "l"(a), "l"(b), "l"(c));
    return d;
}

__global__ __launch_bounds__(128, 5) void gj_solve_kernel(
    const float* __restrict__ input,     // [B, C, H, W]
    const float* __restrict__ weight,    // [B, C*C, H, W]
    const float* __restrict__ logdet_in, // [B]
    float* __restrict__ out)             // z [B,C,H,W] then logdet [B]
{
    __shared__ float s_w[PIX * MSTR];    // ~37 KB
    __shared__ float s_x[PIX * 32];
    __shared__ float s_z[PIX * 32];
    __shared__ float s_red[128];
    __shared__ int   s_last;

    const int t    = threadIdx.x;
    const int lane = t & 31;
    const int w    = t >> 5;
    const int q0   = blockIdx.x * PIX;
    const int b    = q0 / HW;
    const int qm0  = q0 - b * HW;

    // ---- Phase 1: coalesced global load, stage to smem (transpose to row-major) ----
    const float* wbase = weight + (size_t)b * (size_t)(C * C) * HW + qm0;
    #pragma unroll
    for (int it = 0; it < 16; ++it) {
        int idx = it * 128 + t;
        int c   = idx >> 1;
        int pp  = (idx & 1) << 2;
        float4 v = *reinterpret_cast<const float4*>(wbase + (size_t)c * HW + pp);
        int sb = (c >> 5) * RSTR + (c & 31);
        s_w[(pp + 0) * MSTR + sb] = v.x;
        s_w[(pp + 1) * MSTR + sb] = v.y;
        s_w[(pp + 2) * MSTR + sb] = v.z;
        s_w[(pp + 3) * MSTR + sb] = v.w;
    }
    #pragma unroll
    for (int it = 0; it < 2; ++it) {
        int c = it * 16 + (t >> 3), pp = t & 7;
        s_x[pp * 32 + c] = input[(size_t)b * C * HW + (size_t)c * HW + qm0 + pp];
    }
    __syncthreads();

    // ---- Phase 2: Gauss-Jordan ----
    // mat = lane>>4, par = (lane>>3)&1, sg = lane&7.
    // Lane owns rows sg+8t (t=0..3), f32x2 blocks 2s+par (s=0..7) of matrix mat.
    const int mat = lane >> 4;
    const int par = (lane >> 3) & 1;
    const int sg  = lane & 7;
    const int pix = 2 * w + mat;

    unsigned long long d[4][8];
    {
        const float* rb = s_w + pix * MSTR + 2 * par;
        #pragma unroll
        for (int tt = 0; tt < 4; ++tt) {
            const float* rp = rb + (sg + 8 * tt) * RSTR;
            #pragma unroll
            for (int s = 0; s < 8; ++s)
                d[tt][s] = *reinterpret_cast<const unsigned long long*>(rp + 4 * s);
        }
    }
    float rhs[4];
    #pragma unroll
    for (int tt = 0; tt < 4; ++tt)
        rhs[tt] = s_x[pix * 32 + sg + 8 * tt];

    float psave[4] = {1.0f, 1.0f, 1.0f, 1.0f};   // pivots owned (reciprocal NOT kept)

    // ---- pipeline prologue: multipliers for k=0 (column 0 is original data) ----
    unsigned long long nm[4];   // per-row packed negated multipliers for current k
    float rkv;                  // pivot-row rhs for current k
    {
        float e0 = lo32(d[0][0]), e1 = lo32(d[1][0]);
        float e2 = lo32(d[2][0]), e3 = lo32(d[3][0]);
        const float pe = __shfl_sync(FULL_MASK, e0, 0, 16);   // src lane: par=0, sg=0
        const float np = -__fdividef(1.0f, pe);
        float m0 = e0 * np, m1 = e1 * np, m2 = e2 * np, m3 = e3 * np;
        if (sg == 0 && par == 0) { m0 = 0.0f; psave[0] = pe; }
        const int src = (lane & 16) | sg;                     // parity-0 sibling
        unsigned long long mm01 = __shfl_sync(FULL_MASK, pack2(m0, m1), src, 32);
        unsigned long long mm23 = __shfl_sync(FULL_MASK, pack2(m2, m3), src, 32);
        nm[0] = pack2(lo32(mm01), lo32(mm01));
        nm[1] = pack2(hi32(mm01), hi32(mm01));
        nm[2] = pack2(lo32(mm23), lo32(mm23));
        nm[3] = pack2(hi32(mm23), hi32(mm23));
        rkv = __shfl_sync(FULL_MASK, rhs[0], 0, 8);
    }

    #pragma unroll
    for (int k = 0; k < 32; ++k) {
        const int s0 = k >> 2;
        const int ow = k & 7;
        const int tk = k >> 3;
        const int kn = k + 1;
        const int sn = (k < 31) ? (kn >> 2) : s0;

        // head: broadcast + consume the next-pivot slot FIRST
        const unsigned long long usn = __shfl_sync(FULL_MASK, d[tk][sn], ow, 8);
        d[0][sn] = ffma2(nm[0], usn, d[0][sn]);
        d[1][sn] = ffma2(nm[1], usn, d[1][sn]);
        d[2][sn] = ffma2(nm[2], usn, d[2][sn]);
        d[3][sn] = ffma2(nm[3], usn, d[3][sn]);

        // prefetch multipliers for k+1 (overlaps remaining updates)
        unsigned long long nmN[4] = {0, 0, 0, 0};
        if (k < 31) {
            const int pkn = (kn >> 1) & 1;
            const int own = kn & 7;
            const int tkn = kn >> 3;
            float e[4];
            #pragma unroll
            for (int tt = 0; tt < 4; ++tt)
                e[tt] = (kn & 1) ? hi32(d[tt][sn]) : lo32(d[tt][sn]);
            float etk = (tkn == 0) ? e[0] : (tkn == 1) ? e[1] : (tkn == 2) ? e[2] : e[3];
            const float pe = __shfl_sync(FULL_MASK, etk, pkn * 8 + own, 16);
            const float np = -__fdividef(1.0f, pe);
            float m0 = e[0] * np, m1 = e[1] * np, m2 = e[2] * np, m3 = e[3] * np;
            if (sg == own && par == pkn) {
                if (tkn == 0) m0 = 0.0f; else if (tkn == 1) m1 = 0.0f;
                else if (tkn == 2) m2 = 0.0f; else m3 = 0.0f;
                psave[tkn] = pe;
            }
            const int src = (lane & 16) | (pkn << 3) | sg;
            unsigned long long mm01 = __shfl_sync(FULL_MASK, pack2(m0, m1), src, 32);
            unsigned long long mm23 = __shfl_sync(FULL_MASK, pack2(m2, m3), src, 32);
            nmN[0] = pack2(lo32(mm01), lo32(mm01));
            nmN[1] = pack2(hi32(mm01), hi32(mm01));
            nmN[2] = pack2(lo32(mm23), lo32(mm23));
            nmN[3] = pack2(hi32(mm23), hi32(mm23));
        }

        // remaining slots: broadcast interleaved with consumption
        #pragma unroll
        for (int s = s0; s < 8; ++s) {
            if (s == sn) continue;
            const unsigned long long us = __shfl_sync(FULL_MASK, d[tk][s], ow, 8);
            d[0][s] = ffma2(nm[0], us, d[0][s]);
            d[1][s] = ffma2(nm[1], us, d[1][s]);
            d[2][s] = ffma2(nm[2], us, d[2][s]);
            d[3][s] = ffma2(nm[3], us, d[3][s]);
        }
        rhs[0] = fmaf(lo32(nm[0]), rkv, rhs[0]);
        rhs[1] = fmaf(lo32(nm[1]), rkv, rhs[1]);
        rhs[2] = fmaf(lo32(nm[2]), rkv, rhs[2]);
        rhs[3] = fmaf(lo32(nm[3]), rkv, rhs[3]);

        if (k < 31) {
            rkv = __shfl_sync(FULL_MASK, rhs[kn >> 3], kn & 7, 8);
            nm[0] = nmN[0]; nm[1] = nmN[1]; nm[2] = nmN[2]; nm[3] = nmN[3];
        }
    }

    // lane with par == bit1(sg) captured all 4 pivots of its rows; others log(1)=0
    const bool match = (((sg >> 1) & 1) == par);

    float la = __logf(fabsf(psave[0])) + __logf(fabsf(psave[1]))
             + __logf(fabsf(psave[2])) + __logf(fabsf(psave[3]));
    #pragma unroll
    for (int off = 8; off; off >>= 1) la += __shfl_xor_sync(FULL_MASK, la, off, 16);
    if ((lane & 15) == 0) g_pixlogdet[q0 + pix] = la;

    if (match) {
        #pragma unroll
        for (int tt = 0; tt < 4; ++tt)
            s_z[pix * 32 + sg + 8 * tt] = __fdividef(rhs[tt], psave[tt]);
    }
    __syncthreads();

    // ---- Phase 3: coalesced store of z ----
    #pragma unroll
    for (int it = 0; it < 2; ++it) {
        int c = it * 16 + (t >> 3), pp = t & 7;
        out[(size_t)b * C * HW + (size_t)c * HW + qm0 + pp] = s_z[pp * 32 + c];
    }

    // ---- Phase 4: last block per batch reduces the 2304 pixel logdets ----
    __threadfence();
    if (t == 0) {
        int v = atomicAdd(&g_done[b], 1);
        s_last = (v == BLOCKS_PER_BATCH - 1);
    }
    __syncthreads();
    if (s_last) {
        __threadfence();
        float acc = 0.0f;
        #pragma unroll
        for (int r = 0; r < 18; ++r)                 // 2304 = 18 * 128, fixed order
            acc += g_pixlogdet[b * HW + r * 128 + t];
        s_red[t] = acc;
        __syncthreads();
        #pragma unroll
        for (int off = 64; off; off >>= 1) {
            if (t < off) s_red[t] += s_red[t + off];
            __syncthreads();
        }
        if (t == 0) {
            out[(size_t)B * C * HW + b] = logdet_in[b] - s_red[0];
            g_done[b] = 0;                           // reset for next graph replay
        }
    }
}

extern "C" void kernel_launch(void* const* d_in, const int* in_sizes, int n_in,
                              void* d_out, int out_size)
{
    const float* input  = (const float*)d_in[0];
    const float* weight = (const float*)d_in[1];
    const float* logdet = (const float*)d_in[2];
    float* out = (float*)d_out;

    gj_solve_kernel<<<(B * HW) / PIX, 128>>>(input, weight, logdet, out);
}

// round 12
// speedup vs baseline: 1.3979x; 1.3979x over previous
#include <cuda_runtime.h>

// InvConditionalLinear forward: per-pixel 32x32 solve W z = x, sum log|det W|.
// B=16, C=32, H=W=48 (HW=2304). 2 matrices per warp x 2 column-parity slices
// (four 8-lane subgroups). Lane owns 4 rows x 8 f32x2 blocks of its parity.
// R7-validated software-pipelined inner loop (verbatim). Natural registers,
// NO launch-bounds cap (caps spill: R4/R8/R11). Only delta vs R7: s_x/s_z
// row stride 32 -> 33 to break the 8-way bank conflicts in rhs read / z store.

#define FULL_MASK 0xffffffffu

static constexpr int B = 16, C = 32, HW = 48 * 48;     // 2304
static constexpr int PIX = 8;                          // pixels per block (128 thr)
static constexpr int RSTR = 36;                        // row stride (floats)
static constexpr int MSTR = 1156;                      // pixel stride: !=0 mod 8 banks
static constexpr int XSTR = 33;                        // s_x/s_z row stride (conflict fix)
static constexpr int BLOCKS_PER_BATCH = HW / PIX;      // 288

static __device__ float g_pixlogdet[B * HW];
static __device__ int   g_done[B];

__device__ __forceinline__ unsigned long long pack2(float x, float y) {
    unsigned long long r;
    asm("mov.b64 %0, {%1, %2};" : "=l"(r) : "r"(__float_as_uint(x)), "r"(__float_as_uint(y)));
    return r;
}
__device__ __forceinline__ float lo32(unsigned long long v) { return __uint_as_float((unsigned)v); }
__device__ __forceinline__ float hi32(unsigned long long v) { return __uint_as_float((unsigned)(v >> 32)); }
__device__ __forceinline__ unsigned long long ffma2(unsigned long long a, unsigned long long b,
                                                    unsigned long long c) {
    unsigned long long d;
    asm("fma.rn.f32x2 %0, %1, %2, %3;" : "=l"(d) : "l"(a), "l"(b), "l"(c));
    return d;
}

__global__ __launch_bounds__(128) void gj_solve_kernel(
    const float* __restrict__ input,     // [B, C, H, W]
    const float* __restrict__ weight,    // [B, C*C, H, W]
    const float* __restrict__ logdet_in, // [B]
    float* __restrict__ out)             // z [B,C,H,W] then logdet [B]
{
    __shared__ float s_w[PIX * MSTR];    // ~37 KB
    __shared__ float s_x[PIX * XSTR];
    __shared__ float s_z[PIX * XSTR];
    __shared__ float s_red[128];
    __shared__ int   s_last;

    const int t    = threadIdx.x;
    const int lane = t & 31;
    const int w    = t >> 5;
    const int q0   = blockIdx.x * PIX;
    const int b    = q0 / HW;
    const int qm0  = q0 - b * HW;

    // ---- Phase 1: coalesced global load, stage to smem (transpose to row-major) ----
    const float* wbase = weight + (size_t)b * (size_t)(C * C) * HW + qm0;
    #pragma unroll
    for (int it = 0; it < 16; ++it) {
        int idx = it * 128 + t;
        int c   = idx >> 1;
        int pp  = (idx & 1) << 2;
        float4 v = *reinterpret_cast<const float4*>(wbase + (size_t)c * HW + pp);
        int sb = (c >> 5) * RSTR + (c & 31);
        s_w[(pp + 0) * MSTR + sb] = v.x;
        s_w[(pp + 1) * MSTR + sb] = v.y;
        s_w[(pp + 2) * MSTR + sb] = v.z;
        s_w[(pp + 3) * MSTR + sb] = v.w;
    }
    #pragma unroll
    for (int it = 0; it < 2; ++it) {
        int c = it * 16 + (t >> 3), pp = t & 7;
        s_x[pp * XSTR + c] = input[(size_t)b * C * HW + (size_t)c * HW + qm0 + pp];
    }
    __syncthreads();

    // ---- Phase 2: Gauss-Jordan (R7 inner loop, verbatim) ----
    // mat = lane>>4, par = (lane>>3)&1, sg = lane&7.
    // Lane owns rows sg+8t (t=0..3), f32x2 blocks 2s+par (s=0..7) of matrix mat.
    const int mat = lane >> 4;
    const int par = (lane >> 3) & 1;
    const int sg  = lane & 7;
    const int pix = 2 * w + mat;

    unsigned long long d[4][8];
    {
        const float* rb = s_w + pix * MSTR + 2 * par;
        #pragma unroll
        for (int tt = 0; tt < 4; ++tt) {
            const float* rp = rb + (sg + 8 * tt) * RSTR;
            #pragma unroll
            for (int s = 0; s < 8; ++s)
                d[tt][s] = *reinterpret_cast<const unsigned long long*>(rp + 4 * s);
        }
    }
    float rhs[4];
    #pragma unroll
    for (int tt = 0; tt < 4; ++tt)
        rhs[tt] = s_x[pix * XSTR + sg + 8 * tt];

    float psave[4]  = {1.0f, 1.0f, 1.0f, 1.0f};
    float pisave[4] = {1.0f, 1.0f, 1.0f, 1.0f};

    // ---- pipeline prologue: multipliers for k=0 (column 0 is original data) ----
    unsigned long long nm[4];   // per-row packed negated multipliers for current k
    float rkv;                  // pivot-row rhs for current k
    {
        float e0 = lo32(d[0][0]), e1 = lo32(d[1][0]);
        float e2 = lo32(d[2][0]), e3 = lo32(d[3][0]);
        const float pe = __shfl_sync(FULL_MASK, e0, 0, 16);   // src lane: par=0, sg=0
        const float np = -__fdividef(1.0f, pe);
        float m0 = e0 * np, m1 = e1 * np, m2 = e2 * np, m3 = e3 * np;
        if (sg == 0 && par == 0) { m0 = 0.0f; psave[0] = pe; pisave[0] = -np; }
        const int src = (lane & 16) | sg;                     // parity-0 sibling
        unsigned long long mm01 = __shfl_sync(FULL_MASK, pack2(m0, m1), src, 32);
        unsigned long long mm23 = __shfl_sync(FULL_MASK, pack2(m2, m3), src, 32);
        nm[0] = pack2(lo32(mm01), lo32(mm01));
        nm[1] = pack2(hi32(mm01), hi32(mm01));
        nm[2] = pack2(lo32(mm23), lo32(mm23));
        nm[3] = pack2(hi32(mm23), hi32(mm23));
        rkv = __shfl_sync(FULL_MASK, rhs[0], 0, 8);
    }

    #pragma unroll
    for (int k = 0; k < 32; ++k) {
        const int s0 = k >> 2;
        const int ow = k & 7;
        const int tk = k >> 3;
        const int kn = k + 1;
        const int sn = (k < 31) ? (kn >> 2) : s0;

        // head: broadcast + consume the next-pivot slot FIRST
        const unsigned long long usn = __shfl_sync(FULL_MASK, d[tk][sn], ow, 8);
        d[0][sn] = ffma2(nm[0], usn, d[0][sn]);
        d[1][sn] = ffma2(nm[1], usn, d[1][sn]);
        d[2][sn] = ffma2(nm[2], usn, d[2][sn]);
        d[3][sn] = ffma2(nm[3], usn, d[3][sn]);

        // prefetch multipliers for k+1 (overlaps remaining updates)
        unsigned long long nmN[4] = {0, 0, 0, 0};
        if (k < 31) {
            const int pkn = (kn >> 1) & 1;
            const int own = kn & 7;
            const int tkn = kn >> 3;
            float e[4];
            #pragma unroll
            for (int tt = 0; tt < 4; ++tt)
                e[tt] = (kn & 1) ? hi32(d[tt][sn]) : lo32(d[tt][sn]);
            float etk = (tkn == 0) ? e[0] : (tkn == 1) ? e[1] : (tkn == 2) ? e[2] : e[3];
            const float pe = __shfl_sync(FULL_MASK, etk, pkn * 8 + own, 16);
            const float np = -__fdividef(1.0f, pe);
            float m0 = e[0] * np, m1 = e[1] * np, m2 = e[2] * np, m3 = e[3] * np;
            if (sg == own && par == pkn) {
                if (tkn == 0) m0 = 0.0f; else if (tkn == 1) m1 = 0.0f;
                else if (tkn == 2) m2 = 0.0f; else m3 = 0.0f;
                psave[tkn] = pe; pisave[tkn] = -np;
            }
            const int src = (lane & 16) | (pkn << 3) | sg;
            unsigned long long mm01 = __shfl_sync(FULL_MASK, pack2(m0, m1), src, 32);
            unsigned long long mm23 = __shfl_sync(FULL_MASK, pack2(m2, m3), src, 32);
            nmN[0] = pack2(lo32(mm01), lo32(mm01));
            nmN[1] = pack2(hi32(mm01), hi32(mm01));
            nmN[2] = pack2(lo32(mm23), lo32(mm23));
            nmN[3] = pack2(hi32(mm23), hi32(mm23));
        }

        // remaining slots: broadcast interleaved with consumption
        #pragma unroll
        for (int s = s0; s < 8; ++s) {
            if (s == sn) continue;
            const unsigned long long us = __shfl_sync(FULL_MASK, d[tk][s], ow, 8);
            d[0][s] = ffma2(nm[0], us, d[0][s]);
            d[1][s] = ffma2(nm[1], us, d[1][s]);
            d[2][s] = ffma2(nm[2], us, d[2][s]);
            d[3][s] = ffma2(nm[3], us, d[3][s]);
        }
        rhs[0] = fmaf(lo32(nm[0]), rkv, rhs[0]);
        rhs[1] = fmaf(lo32(nm[1]), rkv, rhs[1]);
        rhs[2] = fmaf(lo32(nm[2]), rkv, rhs[2]);
        rhs[3] = fmaf(lo32(nm[3]), rkv, rhs[3]);

        if (k < 31) {
            rkv = __shfl_sync(FULL_MASK, rhs[kn >> 3], kn & 7, 8);
            nm[0] = nmN[0]; nm[1] = nmN[1]; nm[2] = nmN[2]; nm[3] = nmN[3];
        }
    }

    // lane with par == bit1(sg) captured all 4 pivots of its rows; others log(1)=0
    const bool match = (((sg >> 1) & 1) == par);

    float la = __logf(fabsf(psave[0])) + __logf(fabsf(psave[1]))
             + __logf(fabsf(psave[2])) + __logf(fabsf(psave[3]));
    #pragma unroll
    for (int off = 8; off; off >>= 1) la += __shfl_xor_sync(FULL_MASK, la, off, 16);
    if ((lane & 15) == 0) g_pixlogdet[q0 + pix] = la;

    if (match) {
        #pragma unroll
        for (int tt = 0; tt < 4; ++tt)
            s_z[pix * XSTR + sg + 8 * tt] = rhs[tt] * pisave[tt];
    }
    __syncthreads();

    // ---- Phase 3: coalesced store of z ----
    #pragma unroll
    for (int it = 0; it < 2; ++it) {
        int c = it * 16 + (t >> 3), pp = t & 7;
        out[(size_t)b * C * HW + (size_t)c * HW + qm0 + pp] = s_z[pp * XSTR + c];
    }

    // ---- Phase 4: last block per batch reduces the 2304 pixel logdets ----
    __threadfence();
    if (t == 0) {
        int v = atomicAdd(&g_done[b], 1);
        s_last = (v == BLOCKS_PER_BATCH - 1);
    }
    __syncthreads();
    if (s_last) {
        __threadfence();
        float acc = 0.0f;
        #pragma unroll
        for (int r = 0; r < 18; ++r)                 // 2304 = 18 * 128, fixed order
            acc += g_pixlogdet[b * HW + r * 128 + t];
        s_red[t] = acc;
        __syncthreads();
        #pragma unroll
        for (int off = 64; off; off >>= 1) {
            if (t < off) s_red[t] += s_red[t + off];
            __syncthreads();
        }
        if (t == 0) {
            out[(size_t)B * C * HW + b] = logdet_in[b] - s_red[0];
            g_done[b] = 0;                           // reset for next graph replay
        }
    }
}

extern "C" void kernel_launch(void* const* d_in, const int* in_sizes, int n_in,
                              void* d_out, int out_size)
{
    const float* input  = (const float*)d_in[0];
    const float* weight = (const float*)d_in[1];
    const float* logdet = (const float*)d_in[2];
    float* out = (float*)d_out;

    gj_solve_kernel<<<(B * HW) / PIX, 128>>>(input, weight, logdet, out);
}

// round 13
// speedup vs baseline: 1.4020x; 1.0030x over previous
#include <cuda_runtime.h>

// InvConditionalLinear forward: per-pixel 32x32 solve W z = x, sum log|det W|.
// B=16, C=32, H=W=48 (HW=2304). 2 matrices per warp x 2 column-parity slices
// (four 8-lane subgroups). Lane owns 4 rows x 8 f32x2 blocks of its parity.
// RANK-2 super-iterations: columns (2j, 2j+1) eliminated together (they share
// one f32x2 block of one parity). Pivot rows broadcast RAW; the second-row
// correction folds into the multipliers: M0 = m0 - m1*c1, M1 = m1 with
// c1 = u1[j].lo/piv0, piv1 = u1[j].hi - c1*u0[j].hi. 16 super-iterations
// halve the serial chain overhead at identical shuffle/FFMA2 counts.

#define FULL_MASK 0xffffffffu
typedef unsigned long long ull;

static constexpr int B = 16, C = 32, HW = 48 * 48;     // 2304
static constexpr int PIX = 8;                          // pixels per block (128 thr)
static constexpr int RSTR = 36;                        // row stride (floats)
static constexpr int MSTR = 1156;                      // pixel stride: !=0 mod 8 banks
static constexpr int XSTR = 33;                        // s_x/s_z row stride
static constexpr int BLOCKS_PER_BATCH = HW / PIX;      // 288

static __device__ float g_pixlogdet[B * HW];
static __device__ int   g_done[B];

__device__ __forceinline__ ull pack2(float x, float y) {
    ull r;
    asm("mov.b64 %0, {%1, %2};" : "=l"(r) : "r"(__float_as_uint(x)), "r"(__float_as_uint(y)));
    return r;
}
__device__ __forceinline__ float lo32(ull v) { return __uint_as_float((unsigned)v); }
__device__ __forceinline__ float hi32(ull v) { return __uint_as_float((unsigned)(v >> 32)); }
__device__ __forceinline__ ull ffma2(ull a, ull b, ull c) {
    ull d;
    asm("fma.rn.f32x2 %0, %1, %2, %3;" : "=l"(d) : "l"(a), "l"(b), "l"(c));
    return d;
}

__global__ __launch_bounds__(128) void gj_solve_kernel(
    const float* __restrict__ input,     // [B, C, H, W]
    const float* __restrict__ weight,    // [B, C*C, H, W]
    const float* __restrict__ logdet_in, // [B]
    float* __restrict__ out)             // z [B,C,H,W] then logdet [B]
{
    __shared__ float s_w[PIX * MSTR];    // ~37 KB
    __shared__ float s_x[PIX * XSTR];
    __shared__ float s_z[PIX * XSTR];
    __shared__ float s_red[128];
    __shared__ int   s_last;

    const int t    = threadIdx.x;
    const int lane = t & 31;
    const int w    = t >> 5;
    const int q0   = blockIdx.x * PIX;
    const int b    = q0 / HW;
    const int qm0  = q0 - b * HW;

    // ---- Phase 1: coalesced global load, stage to smem (transpose to row-major) ----
    const float* wbase = weight + (size_t)b * (size_t)(C * C) * HW + qm0;
    #pragma unroll
    for (int it = 0; it < 16; ++it) {
        int idx = it * 128 + t;
        int c   = idx >> 1;
        int pp  = (idx & 1) << 2;
        float4 v = *reinterpret_cast<const float4*>(wbase + (size_t)c * HW + pp);
        int sb = (c >> 5) * RSTR + (c & 31);
        s_w[(pp + 0) * MSTR + sb] = v.x;
        s_w[(pp + 1) * MSTR + sb] = v.y;
        s_w[(pp + 2) * MSTR + sb] = v.z;
        s_w[(pp + 3) * MSTR + sb] = v.w;
    }
    #pragma unroll
    for (int it = 0; it < 2; ++it) {
        int c = it * 16 + (t >> 3), pp = t & 7;
        s_x[pp * XSTR + c] = input[(size_t)b * C * HW + (size_t)c * HW + qm0 + pp];
    }
    __syncthreads();

    // ---- Phase 2: rank-2 Gauss-Jordan ----
    // mat = lane>>4, par = (lane>>3)&1, sg = lane&7.
    // Lane owns rows sg+8r (r=0..3), f32x2 blocks 2s+par (s=0..7) of matrix mat.
    const int mat = lane >> 4;
    const int par = (lane >> 3) & 1;
    const int sg  = lane & 7;
    const int pix = 2 * w + mat;

    ull d[4][8];
    {
        const float* rb = s_w + pix * MSTR + 2 * par;
        #pragma unroll
        for (int r = 0; r < 4; ++r) {
            const float* rp = rb + (sg + 8 * r) * RSTR;
            #pragma unroll
            for (int s = 0; s < 8; ++s)
                d[r][s] = *reinterpret_cast<const ull*>(rp + 4 * s);
        }
    }
    float rhs[4];
    #pragma unroll
    for (int r = 0; r < 4; ++r)
        rhs[r] = s_x[pix * XSTR + sg + 8 * r];

    float psave[4]  = {1.0f, 1.0f, 1.0f, 1.0f};
    float pisave[4] = {1.0f, 1.0f, 1.0f, 1.0f};

    // loop-carried: nmm[r] = pack2(-M0_r, -M1_r) for the CURRENT block; pivot rhs pair
    ull   nmm[4];
    float r0v, r1v;

    // ---- prologue: multipliers for block 0 (cols 0,1; parity 0; slot 0; rows 0,1) ----
    {
        const ull pb0 = __shfl_sync(FULL_MASK, d[0][0], 0, 16);   // row 0 pivot block
        const ull pb1 = __shfl_sync(FULL_MASK, d[0][0], 1, 16);   // row 1 pivot block
        const float pinv0 = __fdividef(1.0f, lo32(pb0));
        const float c1    = lo32(pb1) * pinv0;
        const float piv1  = fmaf(-c1, hi32(pb0), hi32(pb1));
        const float pinv1 = __fdividef(1.0f, piv1);
        ull mmL[4];
        #pragma unroll
        for (int r = 0; r < 4; ++r) {
            float e0 = lo32(d[r][0]), e1 = hi32(d[r][0]);
            float m0 = e0 * pinv0;
            if (r == 0 && sg == 0 && par == 0) { m0 = 0.0f; psave[0] = e0;   pisave[0] = pinv0; }
            float m1 = fmaf(-m0, hi32(pb0), e1) * pinv1;
            if (r == 0 && sg == 1 && par == 0) { m1 = 0.0f; psave[0] = piv1; pisave[0] = pinv1; }
            const float M0 = fmaf(-m1, c1, m0);
            mmL[r] = pack2(-M0, -m1);
        }
        const int src = (lane & 16) | sg;                          // parity-0 sibling
        #pragma unroll
        for (int r = 0; r < 4; ++r) nmm[r] = __shfl_sync(FULL_MASK, mmL[r], src, 32);
        r0v = __shfl_sync(FULL_MASK, rhs[0], 0, 8);
        r1v = __shfl_sync(FULL_MASK, rhs[0], 1, 8);
    }

    #pragma unroll
    for (int j = 0; j < 16; ++j) {
        const int s0  = j >> 1;              // conservative first live slot
        const int ow0 = (j & 3) * 2;         // owner lane of row 2j (within subgroup)
        const int ow1 = ow0 + 1;             // owner lane of row 2j+1
        const int tk  = j >> 2;              // owners' local row register index
        const int jn  = j + 1;
        const int sn  = (j < 15) ? (jn >> 1) : 7;   // next pivot block's slot

        // expand duplicated multiplier pairs for FFMA2
        ull nm0[4], nm1[4];
        #pragma unroll
        for (int r = 0; r < 4; ++r) {
            nm0[r] = pack2(lo32(nmm[r]), lo32(nmm[r]));
            nm1[r] = pack2(hi32(nmm[r]), hi32(nmm[r]));
        }

        // head: broadcast + update the NEXT pivot slot first
        {
            const ull u0 = __shfl_sync(FULL_MASK, d[tk][sn], ow0, 8);
            const ull u1 = __shfl_sync(FULL_MASK, d[tk][sn], ow1, 8);
            #pragma unroll
            for (int r = 0; r < 4; ++r)
                d[r][sn] = ffma2(nm0[r], u0, ffma2(nm1[r], u1, d[r][sn]));
        }

        // prefetch multipliers for block j+1 (overlaps the remaining stream)
        ull mmN[4] = {0, 0, 0, 0};
        if (j < 15) {
            const int pn   = jn & 1;
            const int own0 = (jn & 3) * 2;
            const int own1 = own0 + 1;
            const int tkn  = jn >> 2;
            const ull pb0 = __shfl_sync(FULL_MASK, d[tkn][sn], (pn << 3) | own0, 16);
            const ull pb1 = __shfl_sync(FULL_MASK, d[tkn][sn], (pn << 3) | own1, 16);
            const float pinv0 = __fdividef(1.0f, lo32(pb0));
            const float c1    = lo32(pb1) * pinv0;
            const float piv1  = fmaf(-c1, hi32(pb0), hi32(pb1));
            const float pinv1 = __fdividef(1.0f, piv1);
            ull mmL[4];
            #pragma unroll
            for (int r = 0; r < 4; ++r) {
                float e0 = lo32(d[r][sn]), e1 = hi32(d[r][sn]);
                float m0 = e0 * pinv0;
                if (r == tkn) {
                    if (sg == own0 && par == pn) { m0 = 0.0f; psave[r] = e0;   pisave[r] = pinv0; }
                }
                float m1 = fmaf(-m0, hi32(pb0), e1) * pinv1;
                if (r == tkn) {
                    if (sg == own1 && par == pn) { m1 = 0.0f; psave[r] = piv1; pisave[r] = pinv1; }
                }
                const float M0 = fmaf(-m1, c1, m0);
                mmL[r] = pack2(-M0, -m1);
            }
            const int src = (lane & 16) | (pn << 3) | sg;
            #pragma unroll
            for (int r = 0; r < 4; ++r) mmN[r] = __shfl_sync(FULL_MASK, mmL[r], src, 32);
        }

        // stream remaining slots: broadcast raw pivot rows, rank-2 FFMA2 update
        #pragma unroll
        for (int s = s0; s < 8; ++s) {
            if (s == sn) continue;
            const ull u0 = __shfl_sync(FULL_MASK, d[tk][s], ow0, 8);
            const ull u1 = __shfl_sync(FULL_MASK, d[tk][s], ow1, 8);
            #pragma unroll
            for (int r = 0; r < 4; ++r)
                d[r][s] = ffma2(nm0[r], u0, ffma2(nm1[r], u1, d[r][s]));
        }

        // rhs rank-2 update with RAW pivot rhs pair
        #pragma unroll
        for (int r = 0; r < 4; ++r)
            rhs[r] = fmaf(lo32(nm0[r]), r0v, fmaf(lo32(nm1[r]), r1v, rhs[r]));

        // rotate pipeline state (pivot rhs read AFTER this iteration's update)
        if (j < 15) {
            const int tkn = jn >> 2;
            r0v = __shfl_sync(FULL_MASK, rhs[tkn], (jn & 3) * 2, 8);
            r1v = __shfl_sync(FULL_MASK, rhs[tkn], (jn & 3) * 2 + 1, 8);
            #pragma unroll
            for (int r = 0; r < 4; ++r) nmm[r] = mmN[r];
        }
    }

    // lane with par == bit1(sg) captured all 4 pivots of its rows; others log(1)=0
    const bool match = (((sg >> 1) & 1) == par);

    float la = __logf(fabsf(psave[0])) + __logf(fabsf(psave[1]))
             + __logf(fabsf(psave[2])) + __logf(fabsf(psave[3]));
    #pragma unroll
    for (int off = 8; off; off >>= 1) la += __shfl_xor_sync(FULL_MASK, la, off, 16);
    if ((lane & 15) == 0) g_pixlogdet[q0 + pix] = la;

    if (match) {
        #pragma unroll
        for (int r = 0; r < 4; ++r)
            s_z[pix * XSTR + sg + 8 * r] = rhs[r] * pisave[r];
    }
    __syncthreads();

    // ---- Phase 3: coalesced store of z ----
    #pragma unroll
    for (int it = 0; it < 2; ++it) {
        int c = it * 16 + (t >> 3), pp = t & 7;
        out[(size_t)b * C * HW + (size_t)c * HW + qm0 + pp] = s_z[pp * XSTR + c];
    }

    // ---- Phase 4: last block per batch reduces the 2304 pixel logdets ----
    __threadfence();
    if (t == 0) {
        int v = atomicAdd(&g_done[b], 1);
        s_last = (v == BLOCKS_PER_BATCH - 1);
    }
    __syncthreads();
    if (s_last) {
        __threadfence();
        float acc = 0.0f;
        #pragma unroll
        for (int r = 0; r < 18; ++r)                 // 2304 = 18 * 128, fixed order
            acc += g_pixlogdet[b * HW + r * 128 + t];
        s_red[t] = acc;
        __syncthreads();
        #pragma unroll
        for (int off = 64; off; off >>= 1) {
            if (t < off) s_red[t] += s_red[t + off];
            __syncthreads();
        }
        if (t == 0) {
            out[(size_t)B * C * HW + b] = logdet_in[b] - s_red[0];
            g_done[b] = 0;                           // reset for next graph replay
        }
    }
}

extern "C" void kernel_launch(void* const* d_in, const int* in_sizes, int n_in,
                              void* d_out, int out_size)
{
    const float* input  = (const float*)d_in[0];
    const float* weight = (const float*)d_in[1];
    const float* logdet = (const float*)d_in[2];
    float* out = (float*)d_out;

    gj_solve_kernel<<<(B * HW) / PIX, 128>>>(input, weight, logdet, out);
}